// round 15
// baseline (speedup 1.0000x reference)
#include <cuda_runtime.h>
#include <cuda_bf16.h>
#include <math.h>

// x, x_r : (1, 3, 32, 512, 512) fp32. hc=wc=32, 16x16 patches/frame, T=32.
// |(x+1)/2-(xr+1)/2| = |x-xr|/2. Patch elems = 3*32*32 = 3072 (= 768 float4).
// One block per HORIZONTAL PATCH PAIR (4096 x 256): 12 front-batched LDG.128
// per thread, one epilogue barrier for two patches.

#define T_FRAMES 32
#define H_DIM    512
#define W_DIM    512
#define NBLOCKS  (T_FRAMES * 128)              // 4096 (256 patches/frame / 2)
#define CH4      (T_FRAMES * H_DIM * W_DIM / 4)  // channel stride in float4

__device__ int g_frame_max[T_FRAMES] = {0};  // float bits; >= 0 so int atomicMax OK
__device__ unsigned g_done = 0;

__global__ __launch_bounds__(256) void patch_kernel(const float* __restrict__ x,
                                                    const float* __restrict__ xr,
                                                    float* __restrict__ out) {
    const int b   = blockIdx.x;              // 0 .. 4095
    const int t   = b >> 7;                  // frame
    const int pp  = b & 127;                 // patch-pair within frame
    const int ph  = pp >> 3;                 // patch row 0..15
    const int pw2 = (pp & 7) << 1;           // left patch column (0,2,..,14)
    const int tid = threadIdx.x;

    // thread's fixed (row, col4) inside a patch: row = tid>>3, col4 = tid&7
    // base float4 index for the LEFT patch, channel 0 (fits int32)
    const int o4 = ((t * H_DIM + ph * 32 + (tid >> 3)) * W_DIM
                    + pw2 * 32 + ((tid & 7) << 2)) >> 2;

    const float4* px = (const float4*)x  + o4;
    const float4* pr = (const float4*)xr + o4;

    // Front-batch 12 independent LDG.128: {left,right} x {ch0,ch1,ch2} x {x,xr}
    float4 aL0 = px[0];
    float4 aR0 = px[8];                      // +32 floats = right patch
    float4 aL1 = px[CH4];
    float4 aR1 = px[CH4 + 8];
    float4 aL2 = px[2 * CH4];
    float4 aR2 = px[2 * CH4 + 8];
    float4 rL0 = pr[0];
    float4 rR0 = pr[8];
    float4 rL1 = pr[CH4];
    float4 rR1 = pr[CH4 + 8];
    float4 rL2 = pr[2 * CH4];
    float4 rR2 = pr[2 * CH4 + 8];

    float sL = fabsf(aL0.x - rL0.x) + fabsf(aL0.y - rL0.y)
             + fabsf(aL0.z - rL0.z) + fabsf(aL0.w - rL0.w)
             + fabsf(aL1.x - rL1.x) + fabsf(aL1.y - rL1.y)
             + fabsf(aL1.z - rL1.z) + fabsf(aL1.w - rL1.w)
             + fabsf(aL2.x - rL2.x) + fabsf(aL2.y - rL2.y)
             + fabsf(aL2.z - rL2.z) + fabsf(aL2.w - rL2.w);
    float sR = fabsf(aR0.x - rR0.x) + fabsf(aR0.y - rR0.y)
             + fabsf(aR0.z - rR0.z) + fabsf(aR0.w - rR0.w)
             + fabsf(aR1.x - rR1.x) + fabsf(aR1.y - rR1.y)
             + fabsf(aR1.z - rR1.z) + fabsf(aR1.w - rR1.w)
             + fabsf(aR2.x - rR2.x) + fabsf(aR2.y - rR2.y)
             + fabsf(aR2.z - rR2.z) + fabsf(aR2.w - rR2.w);

    // warp reduce both sums
    #pragma unroll
    for (int o = 16; o > 0; o >>= 1) {
        sL += __shfl_xor_sync(0xffffffffu, sL, o);
        sR += __shfl_xor_sync(0xffffffffu, sR, o);
    }

    __shared__ float wsum[16];               // [0..7]=left, [8..15]=right
    const int lane = tid & 31, wid = tid >> 5;
    if (lane == 0) { wsum[wid] = sL; wsum[wid + 8] = sR; }
    __syncthreads();

    if (wid == 0) {
        // lanes 0..7 fold left patch, lanes 8..15 fold right patch
        float v = (lane < 16) ? wsum[lane] : 0.0f;
        v += __shfl_xor_sync(0xffffffffu, v, 1);
        v += __shfl_xor_sync(0xffffffffu, v, 2);
        v += __shfl_xor_sync(0xffffffffu, v, 4);   // lanes 0 and 8 hold patch sums

        bool last = false;
        if ((lane & 7) == 0 && lane < 16) {
            float pm = v * (1.0f / 6144.0f);        // /3072 (mean) and /2
            atomicMax(&g_frame_max[t], __float_as_int(pm));
        }
        if (lane == 0) {
            __threadfence();
            unsigned prev = atomicAdd(&g_done, 1u);
            last = (prev == NBLOCKS - 1);
        }
        last = __shfl_sync(0xffffffffu, (int)last, 0);

        if (last) {
            float fm = __int_as_float(g_frame_max[lane]);   // lane -> frame, >= 0
            float sum = fm;
            #pragma unroll
            for (int o = 16; o > 0; o >>= 1)
                sum += __shfl_xor_sync(0xffffffffu, sum, o);
            if (lane == 0) {
                out[0] = logf(sum * (1.0f / (float)T_FRAMES));
                g_done = 0;                                 // reset for next replay
            }
            g_frame_max[lane] = 0;                          // reset (and clamp at 0)
        }
    }
}

extern "C" void kernel_launch(void* const* d_in, const int* in_sizes, int n_in,
                              void* d_out, int out_size) {
    const float* x  = (const float*)d_in[0];
    const float* xr = (const float*)d_in[1];
    patch_kernel<<<NBLOCKS, 256>>>(x, xr, (float*)d_out);
}